// round 11
// baseline (speedup 1.0000x reference)
#include <cuda_runtime.h>
#include <cuda_bf16.h>

// 2D Haar DWT, single level. (Champion layout, block=512 tail-quantization probe.)
// Input  x  : (B=16, C=64, H=256, W=256) fp32
// Output out: (B, C*4, H/2=128, W/2=128) fp32, planes ordered [cA, cH, cV, cD]
//
// Each thread processes one (bc, h) row position and FOUR output columns:
//   loads 2x float4 from input rows 2h and 2h+1 (4 independent streaming
//   16B loads, 32B inter-thread stride), writes one float4 to each of the
//   4 output planes (dense streaming stores). Identical memory pattern to
//   the converged 73.7us-kernel champion; only CTA shape differs (512 thr).
//
// Converged baseline: ~74us kernel / 6.5 TB/s ncu-DRAM (82% busy) = mixed
// read/write HBM3e turnaround ceiling for the 537MB stream.

#define B_  16
#define C_  64
#define H_  256
#define W_  256
#define H2  (H_/2)          // 128
#define W2  (W_/2)          // 128
#define QUADS (W2/4)        // 32 float4-outputs per output row
#define PLANE (H2*W2)       // 16384 elements per output plane

__global__ __launch_bounds__(512) void dwt_haar_kernel(
    const float* __restrict__ x, float* __restrict__ out)
{
    int idx = blockIdx.x * blockDim.x + threadIdx.x;
    // idx in [0, B*C*H2*QUADS) = 16*64*128*32 = 4,194,304
    int wq = idx & (QUADS - 1);            // which group of 4 output cols
    int h  = (idx >> 5) & (H2 - 1);        // output row
    int bc = idx >> 12;                    // 0 .. B*C-1 = 1023

    const float4* row0 = reinterpret_cast<const float4*>(
        x + (bc * H_ + 2 * h) * W_ + wq * 8);
    const float4* row1 = reinterpret_cast<const float4*>(
        x + (bc * H_ + 2 * h + 1) * W_ + wq * 8);

    // 4 independent streaming loads up front (MLP=4)
    float4 t0 = __ldcs(row0);       // a0 b0 a1 b1
    float4 t1 = __ldcs(row0 + 1);   // a2 b2 a3 b3
    float4 u0 = __ldcs(row1);       // c0 d0 c1 d1
    float4 u1 = __ldcs(row1 + 1);   // c2 d2 c3 d3

    float4 cA, cH, cV, cD;
    {
        float a = t0.x, b = t0.y, c = u0.x, d = u0.y;
        cA.x = (a + b + c + d) * 0.5f;
        cH.x = (c + d - a - b) * 0.5f;
        cV.x = (b + d - a - c) * 0.5f;
        cD.x = (a - b - c + d) * 0.5f;
    }
    {
        float a = t0.z, b = t0.w, c = u0.z, d = u0.w;
        cA.y = (a + b + c + d) * 0.5f;
        cH.y = (c + d - a - b) * 0.5f;
        cV.y = (b + d - a - c) * 0.5f;
        cD.y = (a - b - c + d) * 0.5f;
    }
    {
        float a = t1.x, b = t1.y, c = u1.x, d = u1.y;
        cA.z = (a + b + c + d) * 0.5f;
        cH.z = (c + d - a - b) * 0.5f;
        cV.z = (b + d - a - c) * 0.5f;
        cD.z = (a - b - c + d) * 0.5f;
    }
    {
        float a = t1.z, b = t1.w, c = u1.z, d = u1.w;
        cA.w = (a + b + c + d) * 0.5f;
        cH.w = (c + d - a - b) * 0.5f;
        cV.w = (b + d - a - c) * 0.5f;
        cD.w = (a - b - c + d) * 0.5f;
    }

    // output channel = bc*4 + k ; out[(bc*4 + k)*PLANE + h*W2 + 4*wq]
    float4* obase = reinterpret_cast<float4*>(
        out + (bc * 4) * PLANE + h * W2 + 4 * wq);
    const int pstride = PLANE / 4;   // float4 stride between planes
    __stcs(obase,               cA);
    __stcs(obase + pstride,     cH);
    __stcs(obase + 2 * pstride, cV);
    __stcs(obase + 3 * pstride, cD);
}

extern "C" void kernel_launch(void* const* d_in, const int* in_sizes, int n_in,
                              void* d_out, int out_size) {
    const float* x = (const float*)d_in[0];
    float* out = (float*)d_out;
    int total_threads = B_ * C_ * H2 * QUADS;   // 4,194,304
    int block = 512;
    int grid = total_threads / block;           // 8192
    dwt_haar_kernel<<<grid, block>>>(x, out);
}

// round 12
// speedup vs baseline: 1.0012x; 1.0012x over previous
#include <cuda_runtime.h>
#include <cuda_bf16.h>

// 2D Haar DWT, single level. (FINAL — converged champion, R3 layout.)
// Input  x  : (B=16, C=64, H=256, W=256) fp32
// Output out: (B, C*4, H/2=128, W/2=128) fp32, planes ordered [cA, cH, cV, cD]
//
// Each thread processes one (bc, h) row position and FOUR output columns:
//   loads 2x float4 from input rows 2h and 2h+1 (4 independent streaming
//   16B loads, 32B inter-thread stride = within coalescing tolerance),
//   writes one float4 to each of the 4 output planes (dense streaming stores).
//
// Session conclusion: 73.7-75.1us kernel / ~6.5 TB/s ncu-DRAM (82% busy),
// reproduced 3x. Varied axes — store width, streaming hints, MLP 4/8,
// thread coarsening, warp-per-row, persistent single-wave, block 256/512 —
// all plateau here or regress. This is the mixed read/write HBM3e
// turnaround ceiling for the irreducible 537MB stream; remaining wall-time
// gap (~7us) is harness graph-replay overhead.

#define B_  16
#define C_  64
#define H_  256
#define W_  256
#define H2  (H_/2)          // 128
#define W2  (W_/2)          // 128
#define QUADS (W2/4)        // 32 float4-outputs per output row
#define PLANE (H2*W2)       // 16384 elements per output plane

__global__ __launch_bounds__(256) void dwt_haar_kernel(
    const float* __restrict__ x, float* __restrict__ out)
{
    int idx = blockIdx.x * blockDim.x + threadIdx.x;
    // idx in [0, B*C*H2*QUADS) = 16*64*128*32 = 4,194,304
    int wq = idx & (QUADS - 1);            // which group of 4 output cols
    int h  = (idx >> 5) & (H2 - 1);        // output row
    int bc = idx >> 12;                    // 0 .. B*C-1 = 1023

    const float4* row0 = reinterpret_cast<const float4*>(
        x + (bc * H_ + 2 * h) * W_ + wq * 8);
    const float4* row1 = reinterpret_cast<const float4*>(
        x + (bc * H_ + 2 * h + 1) * W_ + wq * 8);

    // 4 independent streaming loads up front (MLP=4)
    float4 t0 = __ldcs(row0);       // a0 b0 a1 b1
    float4 t1 = __ldcs(row0 + 1);   // a2 b2 a3 b3
    float4 u0 = __ldcs(row1);       // c0 d0 c1 d1
    float4 u1 = __ldcs(row1 + 1);   // c2 d2 c3 d3

    float4 cA, cH, cV, cD;
    {
        float a = t0.x, b = t0.y, c = u0.x, d = u0.y;
        cA.x = (a + b + c + d) * 0.5f;
        cH.x = (c + d - a - b) * 0.5f;
        cV.x = (b + d - a - c) * 0.5f;
        cD.x = (a - b - c + d) * 0.5f;
    }
    {
        float a = t0.z, b = t0.w, c = u0.z, d = u0.w;
        cA.y = (a + b + c + d) * 0.5f;
        cH.y = (c + d - a - b) * 0.5f;
        cV.y = (b + d - a - c) * 0.5f;
        cD.y = (a - b - c + d) * 0.5f;
    }
    {
        float a = t1.x, b = t1.y, c = u1.x, d = u1.y;
        cA.z = (a + b + c + d) * 0.5f;
        cH.z = (c + d - a - b) * 0.5f;
        cV.z = (b + d - a - c) * 0.5f;
        cD.z = (a - b - c + d) * 0.5f;
    }
    {
        float a = t1.z, b = t1.w, c = u1.z, d = u1.w;
        cA.w = (a + b + c + d) * 0.5f;
        cH.w = (c + d - a - b) * 0.5f;
        cV.w = (b + d - a - c) * 0.5f;
        cD.w = (a - b - c + d) * 0.5f;
    }

    // output channel = bc*4 + k ; out[(bc*4 + k)*PLANE + h*W2 + 4*wq]
    float4* obase = reinterpret_cast<float4*>(
        out + (bc * 4) * PLANE + h * W2 + 4 * wq);
    const int pstride = PLANE / 4;   // float4 stride between planes
    __stcs(obase,               cA);
    __stcs(obase + pstride,     cH);
    __stcs(obase + 2 * pstride, cV);
    __stcs(obase + 3 * pstride, cD);
}

extern "C" void kernel_launch(void* const* d_in, const int* in_sizes, int n_in,
                              void* d_out, int out_size) {
    const float* x = (const float*)d_in[0];
    float* out = (float*)d_out;
    int total_threads = B_ * C_ * H2 * QUADS;   // 4,194,304
    int block = 256;
    int grid = total_threads / block;           // 16384
    dwt_haar_kernel<<<grid, block>>>(x, out);
}

// round 13
// speedup vs baseline: 1.0016x; 1.0004x over previous
#include <cuda_runtime.h>
#include <cuda_bf16.h>

// 2D Haar DWT, single level. (FINAL — converged champion, R3 layout.)
// Input  x  : (B=16, C=64, H=256, W=256) fp32
// Output out: (B, C*4, H/2=128, W/2=128) fp32, planes ordered [cA, cH, cV, cD]
//
// Each thread processes one (bc, h) row position and FOUR output columns:
//   loads 2x float4 from input rows 2h and 2h+1 (4 independent streaming
//   16B loads, 32B inter-thread stride = within coalescing tolerance),
//   writes one float4 to each of the 4 output planes (dense streaming stores).
//
// Session conclusion (4x reproduced): 73.7-75.1us kernel / ~6.5 TB/s
// ncu-DRAM (82% busy). All structural axes measured — store width, streaming
// hints, MLP 4/8, thread coarsening, warp-per-row, row-pair warps, persistent
// single-wave, block 256/512 — plateau here or regress. TMA store path and
// HBM-striding ruled out by the B300 LTS path-independence model. This is
// the mixed read/write HBM3e turnaround ceiling for the irreducible 537MB
// stream; the ~7.5us wall-vs-kernel gap is harness graph-replay overhead.

#define B_  16
#define C_  64
#define H_  256
#define W_  256
#define H2  (H_/2)          // 128
#define W2  (W_/2)          // 128
#define QUADS (W2/4)        // 32 float4-outputs per output row
#define PLANE (H2*W2)       // 16384 elements per output plane

__global__ __launch_bounds__(256) void dwt_haar_kernel(
    const float* __restrict__ x, float* __restrict__ out)
{
    int idx = blockIdx.x * blockDim.x + threadIdx.x;
    // idx in [0, B*C*H2*QUADS) = 16*64*128*32 = 4,194,304
    int wq = idx & (QUADS - 1);            // which group of 4 output cols
    int h  = (idx >> 5) & (H2 - 1);        // output row
    int bc = idx >> 12;                    // 0 .. B*C-1 = 1023

    const float4* row0 = reinterpret_cast<const float4*>(
        x + (bc * H_ + 2 * h) * W_ + wq * 8);
    const float4* row1 = reinterpret_cast<const float4*>(
        x + (bc * H_ + 2 * h + 1) * W_ + wq * 8);

    // 4 independent streaming loads up front (MLP=4)
    float4 t0 = __ldcs(row0);       // a0 b0 a1 b1
    float4 t1 = __ldcs(row0 + 1);   // a2 b2 a3 b3
    float4 u0 = __ldcs(row1);       // c0 d0 c1 d1
    float4 u1 = __ldcs(row1 + 1);   // c2 d2 c3 d3

    float4 cA, cH, cV, cD;
    {
        float a = t0.x, b = t0.y, c = u0.x, d = u0.y;
        cA.x = (a + b + c + d) * 0.5f;
        cH.x = (c + d - a - b) * 0.5f;
        cV.x = (b + d - a - c) * 0.5f;
        cD.x = (a - b - c + d) * 0.5f;
    }
    {
        float a = t0.z, b = t0.w, c = u0.z, d = u0.w;
        cA.y = (a + b + c + d) * 0.5f;
        cH.y = (c + d - a - b) * 0.5f;
        cV.y = (b + d - a - c) * 0.5f;
        cD.y = (a - b - c + d) * 0.5f;
    }
    {
        float a = t1.x, b = t1.y, c = u1.x, d = u1.y;
        cA.z = (a + b + c + d) * 0.5f;
        cH.z = (c + d - a - b) * 0.5f;
        cV.z = (b + d - a - c) * 0.5f;
        cD.z = (a - b - c + d) * 0.5f;
    }
    {
        float a = t1.z, b = t1.w, c = u1.z, d = u1.w;
        cA.w = (a + b + c + d) * 0.5f;
        cH.w = (c + d - a - b) * 0.5f;
        cV.w = (b + d - a - c) * 0.5f;
        cD.w = (a - b - c + d) * 0.5f;
    }

    // output channel = bc*4 + k ; out[(bc*4 + k)*PLANE + h*W2 + 4*wq]
    float4* obase = reinterpret_cast<float4*>(
        out + (bc * 4) * PLANE + h * W2 + 4 * wq);
    const int pstride = PLANE / 4;   // float4 stride between planes
    __stcs(obase,               cA);
    __stcs(obase + pstride,     cH);
    __stcs(obase + 2 * pstride, cV);
    __stcs(obase + 3 * pstride, cD);
}

extern "C" void kernel_launch(void* const* d_in, const int* in_sizes, int n_in,
                              void* d_out, int out_size) {
    const float* x = (const float*)d_in[0];
    float* out = (float*)d_out;
    int total_threads = B_ * C_ * H2 * QUADS;   // 4,194,304
    int block = 256;
    int grid = total_threads / block;           // 16384
    dwt_haar_kernel<<<grid, block>>>(x, out);
}

// round 14
// speedup vs baseline: 1.0055x; 1.0039x over previous
#include <cuda_runtime.h>
#include <cuda_bf16.h>

// 2D Haar DWT, single level. (FINAL — converged champion, R3 layout, 5x reproduced.)
// Input  x  : (B=16, C=64, H=256, W=256) fp32
// Output out: (B, C*4, H/2=128, W/2=128) fp32, planes ordered [cA, cH, cV, cD]
//
// Each thread processes one (bc, h) row position and FOUR output columns:
//   loads 2x float4 from input rows 2h and 2h+1 (4 independent streaming
//   16B loads, 32B inter-thread stride = within coalescing tolerance),
//   writes one float4 to each of the 4 output planes (dense streaming stores).
//
// Session conclusion: 73.7-75.1us kernel / ~6.5 TB/s ncu-DRAM (82% busy),
// wall 81.95-82.11us over five runs. All structural axes measured — store
// width, streaming hints, MLP 4/8, thread coarsening, warp-per-row, row-pair
// warps, persistent single-wave, block 256/512 — plateau here or regress.
// TMA store path and HBM striding ruled out by the B300 LTS
// path-independence model. Binding constraint: mixed read/write HBM3e
// turnaround ceiling on the irreducible 537MB stream; the ~7.5us
// wall-vs-kernel gap is harness graph-replay overhead.

#define B_  16
#define C_  64
#define H_  256
#define W_  256
#define H2  (H_/2)          // 128
#define W2  (W_/2)          // 128
#define QUADS (W2/4)        // 32 float4-outputs per output row
#define PLANE (H2*W2)       // 16384 elements per output plane

__global__ __launch_bounds__(256) void dwt_haar_kernel(
    const float* __restrict__ x, float* __restrict__ out)
{
    int idx = blockIdx.x * blockDim.x + threadIdx.x;
    // idx in [0, B*C*H2*QUADS) = 16*64*128*32 = 4,194,304
    int wq = idx & (QUADS - 1);            // which group of 4 output cols
    int h  = (idx >> 5) & (H2 - 1);        // output row
    int bc = idx >> 12;                    // 0 .. B*C-1 = 1023

    const float4* row0 = reinterpret_cast<const float4*>(
        x + (bc * H_ + 2 * h) * W_ + wq * 8);
    const float4* row1 = reinterpret_cast<const float4*>(
        x + (bc * H_ + 2 * h + 1) * W_ + wq * 8);

    // 4 independent streaming loads up front (MLP=4)
    float4 t0 = __ldcs(row0);       // a0 b0 a1 b1
    float4 t1 = __ldcs(row0 + 1);   // a2 b2 a3 b3
    float4 u0 = __ldcs(row1);       // c0 d0 c1 d1
    float4 u1 = __ldcs(row1 + 1);   // c2 d2 c3 d3

    float4 cA, cH, cV, cD;
    {
        float a = t0.x, b = t0.y, c = u0.x, d = u0.y;
        cA.x = (a + b + c + d) * 0.5f;
        cH.x = (c + d - a - b) * 0.5f;
        cV.x = (b + d - a - c) * 0.5f;
        cD.x = (a - b - c + d) * 0.5f;
    }
    {
        float a = t0.z, b = t0.w, c = u0.z, d = u0.w;
        cA.y = (a + b + c + d) * 0.5f;
        cH.y = (c + d - a - b) * 0.5f;
        cV.y = (b + d - a - c) * 0.5f;
        cD.y = (a - b - c + d) * 0.5f;
    }
    {
        float a = t1.x, b = t1.y, c = u1.x, d = u1.y;
        cA.z = (a + b + c + d) * 0.5f;
        cH.z = (c + d - a - b) * 0.5f;
        cV.z = (b + d - a - c) * 0.5f;
        cD.z = (a - b - c + d) * 0.5f;
    }
    {
        float a = t1.z, b = t1.w, c = u1.z, d = u1.w;
        cA.w = (a + b + c + d) * 0.5f;
        cH.w = (c + d - a - b) * 0.5f;
        cV.w = (b + d - a - c) * 0.5f;
        cD.w = (a - b - c + d) * 0.5f;
    }

    // output channel = bc*4 + k ; out[(bc*4 + k)*PLANE + h*W2 + 4*wq]
    float4* obase = reinterpret_cast<float4*>(
        out + (bc * 4) * PLANE + h * W2 + 4 * wq);
    const int pstride = PLANE / 4;   // float4 stride between planes
    __stcs(obase,               cA);
    __stcs(obase + pstride,     cH);
    __stcs(obase + 2 * pstride, cV);
    __stcs(obase + 3 * pstride, cD);
}

extern "C" void kernel_launch(void* const* d_in, const int* in_sizes, int n_in,
                              void* d_out, int out_size) {
    const float* x = (const float*)d_in[0];
    float* out = (float*)d_out;
    int total_threads = B_ * C_ * H2 * QUADS;   // 4,194,304
    int block = 256;
    int grid = total_threads / block;           // 16384
    dwt_haar_kernel<<<grid, block>>>(x, out);
}